// round 1
// baseline (speedup 1.0000x reference)
#include <cuda_runtime.h>

#define N_NODES 100000
#define N_EDGES 500000
#define IN_DIM 16
#define HEADS 4
#define OUT_DIM 128
#define HC 512           // HEADS*OUT_DIM
#define NEG 0.2f

// Scratch (device globals: allocation-free per harness rules)
__device__ float g_xl[(size_t)N_NODES * HC];     // 204.8 MB
__device__ float g_xr[(size_t)N_NODES * HC];     // 204.8 MB
__device__ float g_ex[(size_t)N_EDGES * HEADS];  // 8 MB
__device__ float g_denom[(size_t)N_NODES * HEADS];

// ---------------------------------------------------------------------------
// K1: x_l = X @ W_l + b_l ; x_r = X @ W_r + b_r.
// One thread per output column (512 threads), 128 nodes per block.
// W columns live in registers; X rows staged through smem.
// ---------------------------------------------------------------------------
__global__ __launch_bounds__(512) void proj_kernel(
    const float* __restrict__ X,
    const float* __restrict__ Wl, const float* __restrict__ bl,
    const float* __restrict__ Wr, const float* __restrict__ br)
{
    __shared__ float sx[128 * IN_DIM];
    const int c = threadIdx.x;  // 0..511
    float wl[IN_DIM], wr[IN_DIM];
#pragma unroll
    for (int k = 0; k < IN_DIM; k++) {
        wl[k] = Wl[k * HC + c];
        wr[k] = Wr[k * HC + c];
    }
    const float bcl = bl[c], bcr = br[c];

    const int n0 = blockIdx.x * 128;
    const int nmax = min(128, N_NODES - n0);

    for (int i = threadIdx.x; i < nmax * IN_DIM; i += blockDim.x)
        sx[i] = X[(size_t)n0 * IN_DIM + i];
    __syncthreads();

    for (int n = 0; n < nmax; n++) {
        float al = bcl, ar = bcr;
#pragma unroll
        for (int k = 0; k < IN_DIM; k++) {
            const float xv = sx[n * IN_DIM + k];
            al = fmaf(xv, wl[k], al);
            ar = fmaf(xv, wr[k], ar);
        }
        const size_t o = (size_t)(n0 + n) * HC + c;
        g_xl[o] = al;
        g_xr[o] = ar;
    }
}

// ---------------------------------------------------------------------------
// K2: per-edge GATv2 score. One warp per edge.
// e_h = sum_c att[h,c] * leakyrelu(x_l[src,h,c] + x_r[dst,h,c])
// ex = exp(e_h) (no max-subtraction: |e| < ~8, safe in fp32; ratio identical).
// Accumulate denom[dst,h] via vector red.
// ---------------------------------------------------------------------------
__device__ __forceinline__ float lrelu(float v) { return v > 0.f ? v : NEG * v; }

__global__ __launch_bounds__(256) void score_kernel(
    const int* __restrict__ idx, const float* __restrict__ att)
{
    const int e = blockIdx.x * 8 + (threadIdx.x >> 5);
    if (e >= N_EDGES) return;
    const int lane = threadIdx.x & 31;
    const int src = idx[e];
    const int dst = idx[N_EDGES + e];

    const float4* __restrict__ xls = (const float4*)(g_xl + (size_t)src * HC);
    const float4* __restrict__ xrs = (const float4*)(g_xr + (size_t)dst * HC);
    const float4* __restrict__ att4 = (const float4*)att;

    float eh[HEADS];
#pragma unroll
    for (int h = 0; h < HEADS; h++) {
        const float4 a = xls[h * 32 + lane];
        const float4 b = xrs[h * 32 + lane];
        const float4 w = att4[h * 32 + lane];
        float s = lrelu(a.x + b.x) * w.x;
        s = fmaf(lrelu(a.y + b.y), w.y, s);
        s = fmaf(lrelu(a.z + b.z), w.z, s);
        s = fmaf(lrelu(a.w + b.w), w.w, s);
#pragma unroll
        for (int off = 16; off > 0; off >>= 1)
            s += __shfl_xor_sync(0xffffffffu, s, off);
        eh[h] = s;
    }

    if (lane == 0) {
        float4 ex;
        ex.x = __expf(eh[0]);
        ex.y = __expf(eh[1]);
        ex.z = __expf(eh[2]);
        ex.w = __expf(eh[3]);
        ((float4*)g_ex)[e] = ex;
        asm volatile(
            "red.global.add.v4.f32 [%0], {%1, %2, %3, %4};"
            :: "l"(g_denom + (size_t)dst * HEADS),
               "f"(ex.x), "f"(ex.y), "f"(ex.z), "f"(ex.w)
            : "memory");
    }
}

// ---------------------------------------------------------------------------
// K3: scatter-aggregate. One warp per edge: out[dst] += ex[e] * x_l[src]
// via vectorized global reductions (4B-scalar atomics would be ~4x slower).
// ---------------------------------------------------------------------------
__global__ __launch_bounds__(256) void aggregate_kernel(
    const int* __restrict__ idx, float* __restrict__ out)
{
    const int e = blockIdx.x * 8 + (threadIdx.x >> 5);
    if (e >= N_EDGES) return;
    const int lane = threadIdx.x & 31;
    const int src = idx[e];
    const int dst = idx[N_EDGES + e];

    const float4 w = ((const float4*)g_ex)[e];
    const float ws[HEADS] = {w.x, w.y, w.z, w.w};
    const float4* __restrict__ xls = (const float4*)(g_xl + (size_t)src * HC);
    float4* __restrict__ op = ((float4*)out) + (size_t)dst * (HC / 4);

#pragma unroll
    for (int h = 0; h < HEADS; h++) {
        const float4 v = xls[h * 32 + lane];
        const float s = ws[h];
        asm volatile(
            "red.global.add.v4.f32 [%0], {%1, %2, %3, %4};"
            :: "l"(op + h * 32 + lane),
               "f"(v.x * s), "f"(v.y * s), "f"(v.z * s), "f"(v.w * s)
            : "memory");
    }
}

// ---------------------------------------------------------------------------
// K4: out = out / denom + bias. Guard denom==0 (isolated nodes -> bias).
// ---------------------------------------------------------------------------
__global__ __launch_bounds__(256) void finalize_kernel(
    float* __restrict__ out, const float* __restrict__ bias)
{
    const size_t i = (size_t)blockIdx.x * blockDim.x + threadIdx.x;
    if (i >= (size_t)N_NODES * (HC / 4)) return;
    const int node = (int)(i >> 7);
    const int c4 = (int)(i & 127);
    const int h = c4 >> 5;

    const float d = g_denom[node * HEADS + h];
    const float inv = (d > 0.f) ? (1.0f / d) : 0.f;

    float4 o = ((float4*)out)[i];
    const float4 b = ((const float4*)bias)[c4];
    o.x = fmaf(o.x, inv, b.x);
    o.y = fmaf(o.y, inv, b.y);
    o.z = fmaf(o.z, inv, b.z);
    o.w = fmaf(o.w, inv, b.w);
    ((float4*)out)[i] = o;
}

// ---------------------------------------------------------------------------
extern "C" void kernel_launch(void* const* d_in, const int* in_sizes, int n_in,
                              void* d_out, int out_size)
{
    const float* X    = (const float*)d_in[0];  // [N, 16]
    const int*   idx  = (const int*)  d_in[1];  // [2, E]
    const float* Wl   = (const float*)d_in[2];  // [16, 512]
    const float* bl   = (const float*)d_in[3];  // [512]
    const float* Wr   = (const float*)d_in[4];  // [16, 512]
    const float* br   = (const float*)d_in[5];  // [512]
    const float* att  = (const float*)d_in[6];  // [4, 128]
    const float* bias = (const float*)d_in[7];  // [512]
    float* out = (float*)d_out;                 // [N, 512]

    void* denom_ptr = nullptr;
    cudaGetSymbolAddress(&denom_ptr, g_denom);

    cudaMemsetAsync(out, 0, (size_t)N_NODES * HC * sizeof(float), 0);
    cudaMemsetAsync(denom_ptr, 0, (size_t)N_NODES * HEADS * sizeof(float), 0);

    proj_kernel<<<(N_NODES + 127) / 128, 512>>>(X, Wl, bl, Wr, br);
    score_kernel<<<(N_EDGES + 7) / 8, 256>>>(idx, att);
    aggregate_kernel<<<(N_EDGES + 7) / 8, 256>>>(idx, out);

    const int tot4 = N_NODES * (HC / 4);
    finalize_kernel<<<(tot4 + 255) / 256, 256>>>(out, bias);
}

// round 2
// speedup vs baseline: 1.4950x; 1.4950x over previous
#include <cuda_runtime.h>
#include <cuda_fp16.h>

#define N_NODES 100000
#define N_EDGES 500000
#define IN_DIM 16
#define HEADS 4
#define OUT_DIM 128
#define HC 512           // HEADS*OUT_DIM
#define NEG 0.2f

// Scratch (device globals: allocation-free per harness rules)
__device__ __half g_xl[(size_t)N_NODES * HC];    // 102.4 MB
__device__ __half g_xr[(size_t)N_NODES * HC];    // 102.4 MB
__device__ float  g_denom[(size_t)N_NODES * HEADS];

// ---------------------------------------------------------------------------
// K1: x_l = X @ W_l + b_l ; x_r = X @ W_r + b_r, stored fp16.
// One thread per output column (512 threads), 128 nodes per block.
// ---------------------------------------------------------------------------
__global__ __launch_bounds__(512) void proj_kernel(
    const float* __restrict__ X,
    const float* __restrict__ Wl, const float* __restrict__ bl,
    const float* __restrict__ Wr, const float* __restrict__ br)
{
    __shared__ float sx[128 * IN_DIM];
    const int c = threadIdx.x;  // 0..511
    float wl[IN_DIM], wr[IN_DIM];
#pragma unroll
    for (int k = 0; k < IN_DIM; k++) {
        wl[k] = Wl[k * HC + c];
        wr[k] = Wr[k * HC + c];
    }
    const float bcl = bl[c], bcr = br[c];

    const int n0 = blockIdx.x * 128;
    const int nmax = min(128, N_NODES - n0);

    for (int i = threadIdx.x; i < nmax * IN_DIM; i += blockDim.x)
        sx[i] = X[(size_t)n0 * IN_DIM + i];
    __syncthreads();

    for (int n = 0; n < nmax; n++) {
        float al = bcl, ar = bcr;
#pragma unroll
        for (int k = 0; k < IN_DIM; k++) {
            const float xv = sx[n * IN_DIM + k];
            al = fmaf(xv, wl[k], al);
            ar = fmaf(xv, wr[k], ar);
        }
        const size_t o = (size_t)(n0 + n) * HC + c;
        g_xl[o] = __float2half_rn(al);
        g_xr[o] = __float2half_rn(ar);
    }
}

// ---------------------------------------------------------------------------
// K2 (fused): per-edge score + scatter-aggregate. One warp per edge.
//   e_h  = sum_c att[h,c] * lrelu(x_l[src,h,c] + x_r[dst,h,c])
//   ex_h = exp(e_h)        (no max-subtraction: |e| small, ratio identical)
//   denom[dst,h] += ex_h   (v4 red)
//   out[dst,h,:] += ex_h * x_l[src,h,:]   (v4 reds; x_l reused from registers)
// ---------------------------------------------------------------------------
__device__ __forceinline__ float lrelu(float v) { return v > 0.f ? v : NEG * v; }

__global__ __launch_bounds__(256) void edge_kernel(
    const int* __restrict__ idx, const float* __restrict__ att,
    float* __restrict__ out)
{
    const int e = blockIdx.x * 8 + (threadIdx.x >> 5);
    if (e >= N_EDGES) return;
    const int lane = threadIdx.x & 31;
    const int src = idx[e];
    const int dst = idx[N_EDGES + e];

    // 512 halves per row = 128 uint2; per head: 32 uint2 (one per lane)
    const uint2* __restrict__ xls = ((const uint2*)g_xl) + (size_t)src * 128;
    const uint2* __restrict__ xrs = ((const uint2*)g_xr) + (size_t)dst * 128;
    const float4* __restrict__ att4 = (const float4*)att;

    float xf[HEADS][4];   // x_l payload, kept for the scatter
    float eh[HEADS];

#pragma unroll
    for (int h = 0; h < HEADS; h++) {
        const uint2 ap = xls[h * 32 + lane];
        const uint2 bp = xrs[h * 32 + lane];
        const float2 a0 = __half22float2(*(const __half2*)&ap.x);
        const float2 a1 = __half22float2(*(const __half2*)&ap.y);
        const float2 b0 = __half22float2(*(const __half2*)&bp.x);
        const float2 b1 = __half22float2(*(const __half2*)&bp.y);
        xf[h][0] = a0.x; xf[h][1] = a0.y; xf[h][2] = a1.x; xf[h][3] = a1.y;

        const float4 w = __ldg(&att4[h * 32 + lane]);
        float s = lrelu(a0.x + b0.x) * w.x;
        s = fmaf(lrelu(a0.y + b0.y), w.y, s);
        s = fmaf(lrelu(a1.x + b1.x), w.z, s);
        s = fmaf(lrelu(a1.y + b1.y), w.w, s);
#pragma unroll
        for (int off = 16; off > 0; off >>= 1)
            s += __shfl_xor_sync(0xffffffffu, s, off);
        eh[h] = s;  // all lanes hold the full sum
    }

    float ex[HEADS];
#pragma unroll
    for (int h = 0; h < HEADS; h++) ex[h] = __expf(eh[h]);

    if (lane == 0) {
        asm volatile(
            "red.global.add.v4.f32 [%0], {%1, %2, %3, %4};"
            :: "l"(g_denom + (size_t)dst * HEADS),
               "f"(ex[0]), "f"(ex[1]), "f"(ex[2]), "f"(ex[3])
            : "memory");
    }

    float* __restrict__ op = out + (size_t)dst * HC;
#pragma unroll
    for (int h = 0; h < HEADS; h++) {
        const float s = ex[h];
        asm volatile(
            "red.global.add.v4.f32 [%0], {%1, %2, %3, %4};"
            :: "l"(op + h * OUT_DIM + lane * 4),
               "f"(xf[h][0] * s), "f"(xf[h][1] * s),
               "f"(xf[h][2] * s), "f"(xf[h][3] * s)
            : "memory");
    }
}

// ---------------------------------------------------------------------------
// K3: out = out / denom + bias. Guard denom==0 (isolated nodes -> bias).
// ---------------------------------------------------------------------------
__global__ __launch_bounds__(256) void finalize_kernel(
    float* __restrict__ out, const float* __restrict__ bias)
{
    const size_t i = (size_t)blockIdx.x * blockDim.x + threadIdx.x;
    if (i >= (size_t)N_NODES * (HC / 4)) return;
    const int node = (int)(i >> 7);
    const int c4 = (int)(i & 127);
    const int h = c4 >> 5;

    const float d = g_denom[node * HEADS + h];
    const float inv = (d > 0.f) ? (1.0f / d) : 0.f;

    float4 o = ((float4*)out)[i];
    const float4 b = ((const float4*)bias)[c4];
    o.x = fmaf(o.x, inv, b.x);
    o.y = fmaf(o.y, inv, b.y);
    o.z = fmaf(o.z, inv, b.z);
    o.w = fmaf(o.w, inv, b.w);
    ((float4*)out)[i] = o;
}

// ---------------------------------------------------------------------------
extern "C" void kernel_launch(void* const* d_in, const int* in_sizes, int n_in,
                              void* d_out, int out_size)
{
    const float* X    = (const float*)d_in[0];  // [N, 16]
    const int*   idx  = (const int*)  d_in[1];  // [2, E]
    const float* Wl   = (const float*)d_in[2];  // [16, 512]
    const float* bl   = (const float*)d_in[3];  // [512]
    const float* Wr   = (const float*)d_in[4];  // [16, 512]
    const float* br   = (const float*)d_in[5];  // [512]
    const float* att  = (const float*)d_in[6];  // [4, 128]
    const float* bias = (const float*)d_in[7];  // [512]
    float* out = (float*)d_out;                 // [N, 512]

    void* denom_ptr = nullptr;
    cudaGetSymbolAddress(&denom_ptr, g_denom);

    cudaMemsetAsync(out, 0, (size_t)N_NODES * HC * sizeof(float), 0);
    cudaMemsetAsync(denom_ptr, 0, (size_t)N_NODES * HEADS * sizeof(float), 0);

    proj_kernel<<<(N_NODES + 127) / 128, 512>>>(X, Wl, bl, Wr, br);
    edge_kernel<<<(N_EDGES + 7) / 8, 256>>>(idx, att, out);

    const int tot4 = N_NODES * (HC / 4);
    finalize_kernel<<<(tot4 + 255) / 256, 256>>>(out, bias);
}